// round 16
// baseline (speedup 1.0000x reference)
#include <cuda_runtime.h>
#include <cuda_bf16.h>
#include <cstdint>

// SKA: spatially-varying 3x3 grouped conv.
// x: (B=8, C=64, H=128, W=128) f32
// w: (B=8, C_w=8, 9, H, W) f32
// out[b, g*8+cw, h, col] = sum_{i,j} x_pad[..., h+i-1, col+j-1] * w[b, cw, i*3+j, h, col]
//
// Warp-tile = (b, cw, 4-row band). ROLLING WINDOW: per group a 3-row x window
// (h-1, h, h+1) lives in registers; after each output row it slides down by
// loading ONE new row per group. Per band: 48 x-loads (1.5x logical reads)
// + 36 w-loads (w read exactly once) = 84 LDG per 4 output rows, vs 100 for
// the h-pair tile (R12) -- the R13 traffic cut WITHOUT its 255-reg spills
// (only current row's 9 weight float4s live at a time => ~150 regs).
// L2 policy (proven): loads evict_last (x+w stays L2-resident across graph
// replays), stores evict_first (write stream = eviction victim).
// 2048 band-tiles / 2048 warps = exactly 1 tile per warp (64-thr blocks x1024).

#define B_   8
#define C_   64
#define H_   128
#define W_   128
#define CW_  8
#define G_   8
#define HW_  (H_ * W_)
#define NBANDS 32
#define NTILES (B_ * CW_ * NBANDS)   // 2048 warp-tiles
#define GRID_  1024                  // x2 warps = 2048 warps, 1 tile each

__device__ __forceinline__ float4 ldg_pol(const float* p, uint64_t pol) {
    float4 v;
    asm volatile("ld.global.nc.L2::cache_hint.v4.f32 {%0,%1,%2,%3}, [%4], %5;"
                 : "=f"(v.x), "=f"(v.y), "=f"(v.z), "=f"(v.w)
                 : "l"(p), "l"(pol));
    return v;
}

__device__ __forceinline__ void stg_pol(float* p, float4 v, uint64_t pol) {
    asm volatile("st.global.L2::cache_hint.v4.f32 [%0], {%1,%2,%3,%4}, %5;"
                 :: "l"(p), "f"(v.x), "f"(v.y), "f"(v.z), "f"(v.w), "l"(pol)
                 : "memory");
}

// accumulate one x-row's 3-tap contribution into acc (4 output columns)
__device__ __forceinline__ void row_fma(
    float4 vd, float L, float R,
    float4 wl, float4 wc, float4 wr, float4& a)
{
    a.x = fmaf(L,    wl.x, a.x);
    a.x = fmaf(vd.x, wc.x, a.x);
    a.x = fmaf(vd.y, wr.x, a.x);

    a.y = fmaf(vd.x, wl.y, a.y);
    a.y = fmaf(vd.y, wc.y, a.y);
    a.y = fmaf(vd.z, wr.y, a.y);

    a.z = fmaf(vd.y, wl.z, a.z);
    a.z = fmaf(vd.z, wc.z, a.z);
    a.z = fmaf(vd.w, wr.z, a.z);

    a.w = fmaf(vd.z, wl.w, a.w);
    a.w = fmaf(vd.w, wc.w, a.w);
    a.w = fmaf(R,    wr.w, a.w);
}

__global__ void __launch_bounds__(64, 6) ska_kernel(
    const float* __restrict__ x,
    const float* __restrict__ w,
    float* __restrict__ out)
{
    const int tid  = threadIdx.x;
    const int lane = tid & 31;
    const int q    = tid >> 5;
    const int col0 = lane << 2;

    uint64_t pol_el, pol_ef;
    asm volatile("createpolicy.fractional.L2::evict_last.b64 %0, 1.0;"  : "=l"(pol_el));
    asm volatile("createpolicy.fractional.L2::evict_first.b64 %0, 1.0;" : "=l"(pol_ef));

    const int t    = blockIdx.x * 2 + q;   // 0..2047, exactly one tile per warp
    const int band = t & 31;
    const int cw   = (t >> 5) & 7;
    const int b    = t >> 8;
    const int h0   = band << 2;            // output rows h0 .. h0+3

    const float4 z4 = make_float4(0.f, 0.f, 0.f, 0.f);

    const float* xb = x + (size_t)b * C_ * HW_ + col0;
    const float* wb = w + ((size_t)(b * CW_ + cw) * 9) * HW_ + col0;
    float* ob = out + (size_t)b * C_ * HW_ + col0;

    // rolling 3-row x window per group: rows h-1, h, h+1 for current h
    float4 xw[G_][3];
#pragma unroll
    for (int g = 0; g < G_; g++) {
        int c = g * CW_ + cw;
        const float* xr = xb + (size_t)c * HW_ + h0 * W_;
        xw[g][0] = (h0 > 0) ? ldg_pol(xr - W_, pol_el) : z4;
        xw[g][1] = ldg_pol(xr, pol_el);
        xw[g][2] = ldg_pol(xr + W_, pol_el);   // h0+1 <= 125, always in range
    }

#pragma unroll
    for (int r = 0; r < 4; r++) {
        const int h = h0 + r;

        // 9 per-pixel weights for output row h (each w row read exactly once)
        float4 wv[9];
#pragma unroll
        for (int k = 0; k < 9; k++)
            wv[k] = ldg_pol(wb + (size_t)k * HW_ + h * W_, pol_el);

        const int  hn    = h + 2;                    // row entering the window
        const bool hn_ok = (r < 3) && (hn < H_);

#pragma unroll
        for (int g = 0; g < G_; g++) {
            int c = g * CW_ + cw;

            float L[3], R[3];
#pragma unroll
            for (int rr = 0; rr < 3; rr++) {
                L[rr] = __shfl_up_sync(0xffffffffu, xw[g][rr].w, 1);
                R[rr] = __shfl_down_sync(0xffffffffu, xw[g][rr].x, 1);
                if (lane == 0)  L[rr] = 0.f;
                if (lane == 31) R[rr] = 0.f;
            }

            float4 a = z4;
            row_fma(xw[g][0], L[0], R[0], wv[0], wv[1], wv[2], a);
            row_fma(xw[g][1], L[1], R[1], wv[3], wv[4], wv[5], a);
            row_fma(xw[g][2], L[2], R[2], wv[6], wv[7], wv[8], a);

            stg_pol(ob + (size_t)c * HW_ + h * W_, a, pol_ef);

            // slide the window; the new row is consumed one full group-loop
            // later, so its latency is self-hiding
            if (r < 3) {
                xw[g][0] = xw[g][1];
                xw[g][1] = xw[g][2];
                xw[g][2] = hn_ok ? ldg_pol(xb + (size_t)c * HW_ + hn * W_, pol_el)
                                 : z4;
            }
        }
    }
}

extern "C" void kernel_launch(void* const* d_in, const int* in_sizes, int n_in,
                              void* d_out, int out_size) {
    const float* x = (const float*)d_in[0];
    const float* w = (const float*)d_in[1];
    float* out = (float*)d_out;

    ska_kernel<<<GRID_, 64>>>(x, w, out);
}

// round 17
// speedup vs baseline: 1.0173x; 1.0173x over previous
#include <cuda_runtime.h>
#include <cuda_bf16.h>
#include <cstdint>

// SKA: spatially-varying 3x3 grouped conv.
// x: (B=8, C=64, H=128, W=128) f32
// w: (B=8, C_w=8, 9, H, W) f32
// out[b, g*8+cw, h, col] = sum_{i,j} x_pad[..., h+i-1, col+j-1] * w[b, cw, i*3+j, h, col]
//
// R12 h-pair tile (proven best): warp-tile = (b, cw, h-pair), all 8 groups x
// 2 output rows, 4 x-rows per group shared by both rows, 18 weight float4s
// loaded once per warp. L2 policy: loads evict_last (x+w L2-resident across
// graph replays), stores evict_first.
//
// NEW (R17): group batch 2 -> 4. Evidence from R8-R16 isolates the limiter as
// L2-hit latency x outstanding requests/SM. Batch-4 puts 16 independent
// LDG.128 in flight per burst (vs 8), raising outstanding loads/SM from ~96
// to ~160. 64-thr blocks, __launch_bounds__(64,5) (204-reg cap) to fit the
// ~175-reg tile without spills; 10 warps/SM.

#define B_   8
#define C_   64
#define H_   128
#define W_   128
#define CW_  8
#define G_   8
#define HW_  (H_ * W_)
#define NPAIRS 64
#define NTILES (B_ * CW_ * NPAIRS)   // 4096 warp-tiles
#define GRID_  1024                  // x2 warps = 2048 warps, 2 strided tiles each

__device__ __forceinline__ float4 ldg_pol(const float* p, uint64_t pol) {
    float4 v;
    asm volatile("ld.global.nc.L2::cache_hint.v4.f32 {%0,%1,%2,%3}, [%4], %5;"
                 : "=f"(v.x), "=f"(v.y), "=f"(v.z), "=f"(v.w)
                 : "l"(p), "l"(pol));
    return v;
}

__device__ __forceinline__ void stg_pol(float* p, float4 v, uint64_t pol) {
    asm volatile("st.global.L2::cache_hint.v4.f32 [%0], {%1,%2,%3,%4}, %5;"
                 :: "l"(p), "f"(v.x), "f"(v.y), "f"(v.z), "f"(v.w), "l"(pol)
                 : "memory");
}

// accumulate one x-row's 3-tap contribution into acc (4 output columns)
__device__ __forceinline__ void row_fma(
    float4 vd, float L, float R,
    float4 wl, float4 wc, float4 wr, float4& a)
{
    a.x = fmaf(L,    wl.x, a.x);
    a.x = fmaf(vd.x, wc.x, a.x);
    a.x = fmaf(vd.y, wr.x, a.x);

    a.y = fmaf(vd.x, wl.y, a.y);
    a.y = fmaf(vd.y, wc.y, a.y);
    a.y = fmaf(vd.z, wr.y, a.y);

    a.z = fmaf(vd.y, wl.z, a.z);
    a.z = fmaf(vd.z, wc.z, a.z);
    a.z = fmaf(vd.w, wr.z, a.z);

    a.w = fmaf(vd.z, wl.w, a.w);
    a.w = fmaf(vd.w, wc.w, a.w);
    a.w = fmaf(R,    wr.w, a.w);
}

__device__ __forceinline__ void do_tile(
    int t, int lane, int col0,
    const float* __restrict__ x, const float* __restrict__ w,
    float* __restrict__ out, uint64_t pol_el, uint64_t pol_ef)
{
    int hp = t & 63;
    int cw = (t >> 6) & 7;
    int b  = t >> 9;
    int h0 = hp << 1;              // output rows h0, h0+1

    const bool top = (h0 > 0);
    const bool bot = (h0 < H_ - 2);
    const float4 z4 = make_float4(0.f, 0.f, 0.f, 0.f);

    // ---- 18 per-pixel weights: 9 for row h0, 9 for row h0+1 ----
    const float* wb = w + ((size_t)(b * CW_ + cw) * 9) * HW_ + h0 * W_ + col0;
    float4 wv0[9], wv1[9];
#pragma unroll
    for (int k = 0; k < 9; k++) {
        wv0[k] = ldg_pol(wb + (size_t)k * HW_,      pol_el);
        wv1[k] = ldg_pol(wb + (size_t)k * HW_ + W_, pol_el);
    }

    const float* xb = x + (size_t)b * C_ * HW_ + h0 * W_ + col0;
    float* ob = out + (size_t)b * C_ * HW_ + h0 * W_ + col0;

    // ---- groups in batches of 4: 16 independent LDG.128 per burst ----
#pragma unroll
    for (int gg = 0; gg < G_; gg += 4) {
        float4 v[4][4];   // x rows h0-1, h0, h0+1, h0+2 for 4 groups
#pragma unroll
        for (int p = 0; p < 4; p++) {
            int c = (gg + p) * CW_ + cw;
            const float* xr = xb + (size_t)c * HW_;
            v[p][0] = top ? ldg_pol(xr - W_,     pol_el) : z4;
            v[p][1] =       ldg_pol(xr,          pol_el);
            v[p][2] =       ldg_pol(xr + W_,     pol_el);
            v[p][3] = bot ? ldg_pol(xr + 2 * W_, pol_el) : z4;
        }

#pragma unroll
        for (int p = 0; p < 4; p++) {
            float L[4], R[4];
#pragma unroll
            for (int r = 0; r < 4; r++) {
                L[r] = __shfl_up_sync(0xffffffffu, v[p][r].w, 1);
                R[r] = __shfl_down_sync(0xffffffffu, v[p][r].x, 1);
                if (lane == 0)  L[r] = 0.f;
                if (lane == 31) R[r] = 0.f;
            }

            float4 a0 = z4, a1 = z4;
            row_fma(v[p][0], L[0], R[0], wv0[0], wv0[1], wv0[2], a0);
            row_fma(v[p][1], L[1], R[1], wv0[3], wv0[4], wv0[5], a0);
            row_fma(v[p][2], L[2], R[2], wv0[6], wv0[7], wv0[8], a0);

            row_fma(v[p][1], L[1], R[1], wv1[0], wv1[1], wv1[2], a1);
            row_fma(v[p][2], L[2], R[2], wv1[3], wv1[4], wv1[5], a1);
            row_fma(v[p][3], L[3], R[3], wv1[6], wv1[7], wv1[8], a1);

            int c = (gg + p) * CW_ + cw;
            float* op = ob + (size_t)c * HW_;
            stg_pol(op,      a0, pol_ef);
            stg_pol(op + W_, a1, pol_ef);
        }
    }
}

__global__ void __launch_bounds__(64, 5) ska_kernel(
    const float* __restrict__ x,
    const float* __restrict__ w,
    float* __restrict__ out)
{
    const int tid  = threadIdx.x;
    const int lane = tid & 31;
    const int q    = tid >> 5;
    const int col0 = lane << 2;

    uint64_t pol_el, pol_ef;
    asm volatile("createpolicy.fractional.L2::evict_last.b64 %0, 1.0;"  : "=l"(pol_el));
    asm volatile("createpolicy.fractional.L2::evict_first.b64 %0, 1.0;" : "=l"(pol_ef));

    const int widx = blockIdx.x * 2 + q;    // 0..2047

    do_tile(widx,        lane, col0, x, w, out, pol_el, pol_ef);
    do_tile(widx + 2048, lane, col0, x, w, out, pol_el, pol_ef);
}

extern "C" void kernel_launch(void* const* d_in, const int* in_sizes, int n_in,
                              void* d_out, int out_size) {
    const float* x = (const float*)d_in[0];
    const float* w = (const float*)d_in[1];
    float* out = (float*)d_out;

    ska_kernel<<<GRID_, 64>>>(x, w, out);
}